// round 1
// baseline (speedup 1.0000x reference)
#include <cuda_runtime.h>

// ============================================================================
// OLS_4294967296554: NNLS  min ||[X,1][W;b] - y||^2 s.t. W>=0
// Strategy: compute G = A^T A (33x33) and c = A^T y (33x4) over N=2M rows
// (the only heavy part), then solve the QP with projected gradient descent
// (G is ~N*I, kappa ~1.02 -> ~0.034 contraction per iteration, 40 iters
// reaches fp32 precision; same unique optimum as the reference's FISTA).
// ============================================================================

#define NBLK 1184
#define TILE 64
#define PGD_ITERS 40

// ACC layout:
//   [0..1023]    : Gxx[i][j] = sum X[:,i]*X[:,j]  (i,j < 32, full matrix)
//   [1024..1055] : colsum[i] = sum X[:,i]
//   [1056..1183] : c[i][m]   = sum X[:,i]*y[:,m]
//   [1184..1187] : ysum[m]   = sum y[:,m]
__device__ float ACC[1280];

__global__ void zero_acc_kernel() {
    int t = blockIdx.x * blockDim.x + threadIdx.x;
    if (t < 1280) ACC[t] = 0.0f;
}

__global__ __launch_bounds__(256) void partial_kernel(
    const float* __restrict__ X, const float* __restrict__ Y, int N)
{
    __shared__ float4 sX4[TILE * 8];     // 64 rows x 32 floats
    __shared__ float4 sY4[TILE];         // 64 rows x 4 floats
    __shared__ float  sG[1024];
    __shared__ float  scp[8][32][4];
    __shared__ float  sxp[8][32];
    __shared__ float  syp[8][4];

    const int tid = threadIdx.x;
    const int w   = tid >> 5;          // warp 0..7
    const int l   = tid & 31;          // lane
    const int p   = w & 1;             // column-half parity
    const int rg  = w >> 1;            // row group 0..3 (rows r%4==rg)
    const int ti  = l & 7;             // i-tile 0..7 (i0 = 4*ti)
    const int tj  = (l >> 3) + p * 4;  // j-tile 0..7 (j0 = 4*tj)

    float acc[4][4];
#pragma unroll
    for (int a = 0; a < 4; a++)
#pragma unroll
        for (int b = 0; b < 4; b++) acc[a][b] = 0.0f;

    float cacc[4] = {0.f, 0.f, 0.f, 0.f};
    float sxacc = 0.f;
    float ys[4] = {0.f, 0.f, 0.f, 0.f};

    const int ntiles = (N + TILE - 1) / TILE;
    const float4* Xg4 = (const float4*)X;
    const float4* Yg4 = (const float4*)Y;
    const int total4 = N * 8;  // number of float4 in X (N*32/4), fits in int

    for (int t = blockIdx.x; t < ntiles; t += gridDim.x) {
        // ---- stage tile into shared ----
        const int base = t * 512;  // float4 index of tile start in X
#pragma unroll
        for (int k = 0; k < 2; k++) {
            int gi = base + tid + k * 256;
            float4 v = (gi < total4) ? Xg4[gi] : make_float4(0.f, 0.f, 0.f, 0.f);
            sX4[tid + k * 256] = v;
        }
        if (tid < 64) {
            int gy = t * 64 + tid;
            sY4[tid] = (gy < N) ? Yg4[gy] : make_float4(0.f, 0.f, 0.f, 0.f);
        }
        __syncthreads();

        // ---- G pass: each thread: 4x4 tile of X^T X, rows r%4==rg ----
#pragma unroll
        for (int k = 0; k < 16; k++) {
            int r = rg + 4 * k;
            float4 a4 = sX4[r * 8 + ti];
            float4 b4 = sX4[r * 8 + tj];
            float av[4] = {a4.x, a4.y, a4.z, a4.w};
            float bv[4] = {b4.x, b4.y, b4.z, b4.w};
#pragma unroll
            for (int a = 0; a < 4; a++)
#pragma unroll
                for (int b = 0; b < 4; b++) acc[a][b] += av[a] * bv[b];
        }

        // ---- c pass: rows r%8==w; lane l = column i; 4 outputs per thread ----
#pragma unroll
        for (int k = 0; k < 8; k++) {
            int r = w + 8 * k;
            float x = ((const float*)sX4)[r * 32 + l];
            float4 y4 = sY4[r];
            cacc[0] += x * y4.x;
            cacc[1] += x * y4.y;
            cacc[2] += x * y4.z;
            cacc[3] += x * y4.w;
            sxacc += x;
            if (l == 0) { ys[0] += y4.x; ys[1] += y4.y; ys[2] += y4.z; ys[3] += y4.w; }
        }
        __syncthreads();
    }

    // ---- block reduction: G across the 4 row-groups ----
    for (int ph = 0; ph < 4; ph++) {
        if (rg == ph) {
#pragma unroll
            for (int a = 0; a < 4; a++)
#pragma unroll
                for (int b = 0; b < 4; b++) {
                    int idx = (ti * 4 + a) * 32 + (tj * 4 + b);
                    if (ph == 0) sG[idx] = acc[a][b];
                    else         sG[idx] += acc[a][b];
                }
        }
        __syncthreads();
    }

    // ---- stash per-warp partials for c / colsum / ysum ----
#pragma unroll
    for (int m = 0; m < 4; m++) scp[w][l][m] = cacc[m];
    sxp[w][l] = sxacc;
    if (l == 0) {
#pragma unroll
        for (int m = 0; m < 4; m++) syp[w][m] = ys[m];
    }
    __syncthreads();

    // ---- atomics into global accumulators ----
#pragma unroll
    for (int k = 0; k < 4; k++) {
        int e = tid + 256 * k;
        atomicAdd(&ACC[e], sG[e]);
    }
    if (tid < 128) {
        int i = tid >> 2, m = tid & 3;
        float s = 0.f;
#pragma unroll
        for (int ww = 0; ww < 8; ww++) s += scp[ww][i][m];
        atomicAdd(&ACC[1056 + tid], s);
    }
    if (tid < 32) {
        float s = 0.f;
#pragma unroll
        for (int ww = 0; ww < 8; ww++) s += sxp[ww][tid];
        atomicAdd(&ACC[1024 + tid], s);
    }
    if (tid < 4) {
        float s = 0.f;
#pragma unroll
        for (int ww = 0; ww < 8; ww++) s += syp[ww][tid];
        atomicAdd(&ACC[1184 + tid], s);
    }
}

// ---- single-block QP solver: projected gradient descent ----
__global__ __launch_bounds__(256) void solve_kernel(float* __restrict__ out, float Nf)
{
    __shared__ float G[33 * 33];
    __shared__ float c[33 * 4];
    __shared__ float Z[33 * 4];
    __shared__ float rowsum[33];
    __shared__ float stepSh;

    const int tid = threadIdx.x;

    // assemble G (symmetric fill of bias row/col) and c
    for (int e = tid; e < 1024; e += 256) {
        int i = e >> 5, j = e & 31;
        G[i * 33 + j] = ACC[e];
    }
    if (tid < 32) {
        float s = ACC[1024 + tid];
        G[tid * 33 + 32] = s;
        G[32 * 33 + tid] = s;
    }
    if (tid == 0) G[32 * 33 + 32] = Nf;
    if (tid < 128) c[tid] = ACC[1056 + tid];
    if (tid >= 128 && tid < 132) c[tid] = ACC[1184 + (tid - 128)];
    if (tid < 132) Z[tid] = 0.0f;
    __syncthreads();

    // Lipschitz upper bound via Gershgorin: L = max_i sum_j |G[i][j]| >= lambda_max
    if (tid < 33) {
        float s = 0.f;
        for (int j = 0; j < 33; j++) s += fabsf(G[tid * 33 + j]);
        rowsum[tid] = s;
    }
    __syncthreads();
    if (tid == 0) {
        float L = 0.f;
        for (int i = 0; i < 33; i++) L = fmaxf(L, rowsum[i]);
        stepSh = 1.0f / L;
    }
    __syncthreads();
    const float step = stepSh;

    const int i = tid >> 2;
    const int m = tid & 3;
    for (int it = 0; it < PGD_ITERS; it++) {
        float zn = 0.f;
        if (tid < 132) {
            float dot = 0.f;
#pragma unroll
            for (int j = 0; j < 33; j++) dot += G[i * 33 + j] * Z[j * 4 + m];
            zn = Z[tid] - step * (dot - c[tid]);
            if (i < 32) zn = fmaxf(zn, 0.0f);  // W rows nonneg; bias row free
        }
        __syncthreads();
        if (tid < 132) Z[tid] = zn;
        __syncthreads();
    }

    if (tid < 128) out[tid] = Z[tid];  // W[32][4], row-major
}

extern "C" void kernel_launch(void* const* d_in, const int* in_sizes, int n_in,
                              void* d_out, int out_size)
{
    const float* X = (const float*)d_in[0];
    const float* Y = (const float*)d_in[1];
    const int N = in_sizes[0] / 32;

    zero_acc_kernel<<<5, 256>>>();
    partial_kernel<<<NBLK, 256>>>(X, Y, N);
    solve_kernel<<<1, 256>>>((float*)d_out, (float)N);
}

// round 3
// speedup vs baseline: 1.2754x; 1.2754x over previous
#include <cuda_runtime.h>
#include <cstdint>

// ============================================================================
// NNLS via normal equations, fp32 with packed f32x2 FMA (base sm_100-family
// PTX only -- no arch-'a' features; harness PTX target is plain sm_103).
//   G = A^T A (A=[X,1], 33x33), c = A^T y (33x4) over N=2M rows, then a tiny
//   projected-gradient QP solve (G ~ N*I, kappa~1.02, 48 iters >> enough).
// Gram pass: 64-row tiles, cp.async double-buffered, row-uniform warps
// (broadcast LDS), 8x4 register blocks as f32x2 pairs.
// ============================================================================

#define TPB 256
#define NCTA 296
#define TROWS 64
#define PGD_ITERS 48

// ACC layout:
//   [0..1023]    : G[i][j] = sum X[:,i]*X[:,j]
//   [1024..1055] : colsum[i]
//   [1056..1183] : c[i][m] = sum X[:,i]*y[:,m]
//   [1184..1187] : ysum[m]
__device__ float ACC[1280];

// ---- dynamic smem layout (bytes) ----
#define RAWX_OFF 0          // 2 x [64][32] f32 = 2 x 8192
#define RAWY_OFF 16384      // 2 x [64][4]  f32 = 2 x 1024
#define SG_OFF   18432      // 8 x 1024 f32 = 32768
#define SCP_OFF  51200      // 8 x 32 x 4 f32 = 4096
#define SXP_OFF  55296      // 8 x 32 f32 = 1024
#define SYP_OFF  56320      // 8 x 4 f32 = 128
#define SMEMSZ   56448

typedef unsigned long long u64;

static __device__ __forceinline__ uint32_t s2u(const void* p) {
    uint32_t a;
    asm("{ .reg .u64 t; cvta.to.shared.u64 t, %1; cvt.u32.u64 %0, t; }"
        : "=r"(a) : "l"(p));
    return a;
}

#define CP16(dst, src) \
    asm volatile("cp.async.cg.shared.global [%0], [%1], 16;" :: "r"(dst), "l"(src) : "memory")
#define CP_COMMIT() asm volatile("cp.async.commit_group;" ::: "memory")
#define CP_WAIT1()  asm volatile("cp.async.wait_group 1;" ::: "memory")
#define CP_WAIT0()  asm volatile("cp.async.wait_group 0;" ::: "memory")

static __device__ __forceinline__ void ffma2(u64& d, u64 a, u64 b) {
    asm("fma.rn.f32x2 %0, %1, %2, %0;" : "+l"(d) : "l"(a), "l"(b));
}
static __device__ __forceinline__ u64 dup2(float x) {
    u64 r; unsigned u = __float_as_uint(x);
    asm("mov.b64 %0, {%1, %1};" : "=l"(r) : "r"(u));
    return r;
}
static __device__ __forceinline__ void unpack2(u64 v, float& lo, float& hi) {
    unsigned a, b;
    asm("mov.b64 {%0, %1}, %2;" : "=r"(a), "=r"(b) : "l"(v));
    lo = __uint_as_float(a);
    hi = __uint_as_float(b);
}

// ---------------------------------------------------------------------------
__global__ void zero_acc_kernel() {
    int t = blockIdx.x * blockDim.x + threadIdx.x;
    if (t < 1280) ACC[t] = 0.0f;
}

// ---------------------------------------------------------------------------
__global__ __launch_bounds__(TPB, 2) void gram_kernel(
    const float* __restrict__ X, const float* __restrict__ Y,
    int ntiles, int N)
{
    extern __shared__ char smem[];
    const uint32_t sb = s2u(smem);

    const int tid = threadIdx.x;
    const int w   = tid >> 5;      // warp 0..7 (row-uniform owner: rows r%8==w)
    const int l   = tid & 31;
    const int bi  = (l >> 2) & 3;  // i block: i0 = 8*bi  (8 rows of G)
    const int bj  = l & 3;         // j block
    const int jh  = l >> 4;        // j half: j0 = 8*bj + 4*jh (4 cols of G)
    const int jq4 = 2 * bj + jh;   // float4 column of the j vector

    // accumulators: acc[p][q] is f32x2 for G rows (8bi+2p, 8bi+2p+1), col j0+q
    u64 acc[4][4];
#pragma unroll
    for (int p = 0; p < 4; p++)
#pragma unroll
        for (int q = 0; q < 4; q++) acc[p][q] = 0ull;

    float cacc[4] = {0.f, 0.f, 0.f, 0.f};
    float sxacc = 0.f;
    float ys[4] = {0.f, 0.f, 0.f, 0.f};

    const float4* X4 = (const float4*)X;
    const float4* Y4 = (const float4*)Y;
    const long long total4 = (long long)N * 8;
    const int nloc = (ntiles > (int)blockIdx.x)
                     ? (ntiles - 1 - (int)blockIdx.x) / (int)gridDim.x + 1 : 0;

    // stage local tile i into buffer (i&1); zero-fill out-of-range chunks
    auto stage = [&](int i) {
        long long g = (long long)blockIdx.x + (long long)i * gridDim.x;
        int p = i & 1;
        long long gi = g * 512 + tid;
        uint32_t dx = sb + RAWX_OFF + p * 8192 + tid * 16;
        float4 z = make_float4(0.f, 0.f, 0.f, 0.f);
        if (gi < total4) CP16(dx, X4 + gi);
        else *(float4*)(smem + RAWX_OFF + p * 8192 + tid * 16) = z;
        if (gi + 256 < total4) CP16(dx + 4096, X4 + gi + 256);
        else *(float4*)(smem + RAWX_OFF + p * 8192 + tid * 16 + 4096) = z;
        if (tid < 64) {
            long long gy = g * 64 + tid;
            if (gy < N) CP16(sb + RAWY_OFF + p * 1024 + tid * 16, Y4 + gy);
            else *(float4*)(smem + RAWY_OFF + p * 1024 + tid * 16) = z;
        }
        CP_COMMIT();
    };

    if (nloc > 0) stage(0);

    for (int i = 0; i < nloc; i++) {
        const int p = i & 1;
        if (i + 1 < nloc) { stage(i + 1); CP_WAIT1(); } else { CP_WAIT0(); }
        __syncthreads();

        const float4*     rx  = (const float4*)(smem + RAWX_OFF + p * 8192);
        const ulonglong2* rxu = (const ulonglong2*)rx;
        const float*      sx  = (const float*)rx;
        const float4*     sy  = (const float4*)(smem + RAWY_OFF + p * 1024);

        // ---- G pass: rows r = w + 8k (row-uniform warp -> broadcast LDS) ----
#pragma unroll
        for (int k = 0; k < 8; k++) {
            const int r = w + 8 * k;
            ulonglong2 ia = rxu[r * 8 + 2 * bi];      // (x[i0],x[i0+1]) (x[i0+2],x[i0+3])
            ulonglong2 ib = rxu[r * 8 + 2 * bi + 1];  // (x[i0+4..7]) pairs
            float4     jv = rx [r * 8 + jq4];         // x[j0..j0+3]
            u64 ap[4] = {ia.x, ia.y, ib.x, ib.y};
            u64 bd[4] = {dup2(jv.x), dup2(jv.y), dup2(jv.z), dup2(jv.w)};
#pragma unroll
            for (int pp = 0; pp < 4; pp++)
#pragma unroll
                for (int q = 0; q < 4; q++) ffma2(acc[pp][q], ap[pp], bd[q]);
        }

        // ---- c pass: rows r = w + 8k; lane l = column i ----
#pragma unroll
        for (int k = 0; k < 8; k++) {
            const int r = w + 8 * k;
            float  x  = sx[r * 32 + l];
            float4 y4 = sy[r];
            cacc[0] += x * y4.x;
            cacc[1] += x * y4.y;
            cacc[2] += x * y4.z;
            cacc[3] += x * y4.w;
            sxacc += x;
            if (l == 0) { ys[0] += y4.x; ys[1] += y4.y; ys[2] += y4.z; ys[3] += y4.w; }
        }
        __syncthreads();
    }

    // ---- epilogue: per-warp G slice into smem, then reduce + atomics ----
    {
        float* mg = (float*)(smem + SG_OFF) + w * 1024;
        const int j0 = 8 * bj + 4 * jh;
#pragma unroll
        for (int pp = 0; pp < 4; pp++) {
            const int i0 = 8 * bi + 2 * pp;
#pragma unroll
            for (int q = 0; q < 4; q++) {
                float lo, hi;
                unpack2(acc[pp][q], lo, hi);
                mg[i0 * 32 + j0 + q]       = lo;
                mg[(i0 + 1) * 32 + j0 + q] = hi;
            }
        }
        float* scp = (float*)(smem + SCP_OFF) + w * 128;
#pragma unroll
        for (int m = 0; m < 4; m++) scp[l * 4 + m] = cacc[m];
        ((float*)(smem + SXP_OFF))[w * 32 + l] = sxacc;
        if (l == 0) {
#pragma unroll
            for (int m = 0; m < 4; m++) ((float*)(smem + SYP_OFF))[w * 4 + m] = ys[m];
        }
    }
    __syncthreads();

    {
        const float* sg = (const float*)(smem + SG_OFF);
        for (int e = tid; e < 1024; e += TPB) {
            float s = 0.f;
#pragma unroll
            for (int ww = 0; ww < 8; ww++) s += sg[ww * 1024 + e];
            atomicAdd(&ACC[e], s);
        }
        if (tid < 128) {
            const float* scp = (const float*)(smem + SCP_OFF);
            float s = 0.f;
#pragma unroll
            for (int ww = 0; ww < 8; ww++) s += scp[ww * 128 + tid];
            atomicAdd(&ACC[1056 + tid], s);
        }
        if (tid < 32) {
            const float* sxp = (const float*)(smem + SXP_OFF);
            float s = 0.f;
#pragma unroll
            for (int ww = 0; ww < 8; ww++) s += sxp[ww * 32 + tid];
            atomicAdd(&ACC[1024 + tid], s);
        }
        if (tid < 4) {
            const float* syp = (const float*)(smem + SYP_OFF);
            float s = 0.f;
#pragma unroll
            for (int ww = 0; ww < 8; ww++) s += syp[ww * 4 + tid];
            atomicAdd(&ACC[1184 + tid], s);
        }
    }
}

// ---------------------------------------------------------------------------
__global__ __launch_bounds__(256) void solve_kernel(float* __restrict__ out, float Nf)
{
    __shared__ float G[33 * 33];
    __shared__ float c[132];
    __shared__ float Z[132];
    __shared__ float rowsum[33];
    __shared__ float stepSh;

    const int tid = threadIdx.x;
    for (int e = tid; e < 1024; e += 256) {
        int i = e >> 5, j = e & 31;
        G[i * 33 + j] = ACC[e];
    }
    if (tid < 32) {
        float s = ACC[1024 + tid];
        G[tid * 33 + 32] = s;
        G[32 * 33 + tid] = s;
    }
    if (tid == 0) G[32 * 33 + 32] = Nf;
    if (tid < 128) c[tid] = ACC[1056 + tid];
    if (tid >= 128 && tid < 132) c[tid] = ACC[1184 + (tid - 128)];
    if (tid < 132) Z[tid] = 0.0f;
    __syncthreads();

    if (tid < 33) {
        float s = 0.f;
        for (int j = 0; j < 33; j++) s += fabsf(G[tid * 33 + j]);
        rowsum[tid] = s;
    }
    __syncthreads();
    if (tid == 0) {
        float L = 0.f;
        for (int i = 0; i < 33; i++) L = fmaxf(L, rowsum[i]);
        stepSh = 1.0f / L;
    }
    __syncthreads();
    const float step = stepSh;

    const int i = tid >> 2, m = tid & 3;
    for (int it = 0; it < PGD_ITERS; it++) {
        float zn = 0.f;
        if (tid < 132) {
            float dot = 0.f;
#pragma unroll
            for (int j = 0; j < 33; j++) dot += G[i * 33 + j] * Z[j * 4 + m];
            zn = Z[tid] - step * (dot - c[tid]);
            if (i < 32) zn = fmaxf(zn, 0.0f);
        }
        __syncthreads();
        if (tid < 132) Z[tid] = zn;
        __syncthreads();
    }
    if (tid < 128) out[tid] = Z[tid];
}

// ---------------------------------------------------------------------------
extern "C" void kernel_launch(void* const* d_in, const int* in_sizes, int n_in,
                              void* d_out, int out_size)
{
    const float* X = (const float*)d_in[0];
    const float* Y = (const float*)d_in[1];
    const int N = in_sizes[0] / 32;
    const int ntiles = (N + TROWS - 1) / TROWS;

    cudaFuncSetAttribute(gram_kernel,
                         cudaFuncAttributeMaxDynamicSharedMemorySize, SMEMSZ);

    zero_acc_kernel<<<5, 256>>>();
    gram_kernel<<<NCTA, TPB, SMEMSZ>>>(X, Y, ntiles, N);
    solve_kernel<<<1, 256>>>((float*)d_out, (float)N);
}

// round 4
// speedup vs baseline: 1.3449x; 1.0545x over previous
#include <cuda_runtime.h>
#include <cstdint>

// ============================================================================
// NNLS via normal equations, fp32 with packed f32x2 FMA (base sm_100-family
// PTX only -- no arch-'a' features; harness PTX target is plain sm_103).
//   G = A^T A (A=[X,1], 33x33), c = A^T y (33x4) over N=2M rows, then a tiny
//   projected-gradient QP solve (G ~ N*I, kappa~1.02, 48 iters >> enough).
// Gram pass: 64-row tiles, cp.async double-buffered, row-uniform warps
// (broadcast LDS), 8x4 register blocks as f32x2 pairs.
// ============================================================================

#define TPB 256
#define NCTA 296
#define TROWS 64
#define PGD_ITERS 48

// ACC layout:
//   [0..1023]    : G[i][j] = sum X[:,i]*X[:,j]
//   [1024..1055] : colsum[i]
//   [1056..1183] : c[i][m] = sum X[:,i]*y[:,m]
//   [1184..1187] : ysum[m]
__device__ float ACC[1280];

// ---- dynamic smem layout (bytes) ----
#define RAWX_OFF 0          // 2 x [64][32] f32 = 2 x 8192
#define RAWY_OFF 16384      // 2 x [64][4]  f32 = 2 x 1024
#define SG_OFF   18432      // 8 x 1024 f32 = 32768
#define SCP_OFF  51200      // 8 x 32 x 4 f32 = 4096
#define SXP_OFF  55296      // 8 x 32 f32 = 1024
#define SYP_OFF  56320      // 8 x 4 f32 = 128
#define SMEMSZ   56448

typedef unsigned long long u64;

static __device__ __forceinline__ uint32_t s2u(const void* p) {
    uint32_t a;
    asm("{ .reg .u64 t; cvta.to.shared.u64 t, %1; cvt.u32.u64 %0, t; }"
        : "=r"(a) : "l"(p));
    return a;
}

#define CP16(dst, src) \
    asm volatile("cp.async.cg.shared.global [%0], [%1], 16;" :: "r"(dst), "l"(src) : "memory")
#define CP_COMMIT() asm volatile("cp.async.commit_group;" ::: "memory")
#define CP_WAIT1()  asm volatile("cp.async.wait_group 1;" ::: "memory")
#define CP_WAIT0()  asm volatile("cp.async.wait_group 0;" ::: "memory")

static __device__ __forceinline__ void ffma2(u64& d, u64 a, u64 b) {
    asm("fma.rn.f32x2 %0, %1, %2, %0;" : "+l"(d) : "l"(a), "l"(b));
}
static __device__ __forceinline__ u64 dup2(float x) {
    u64 r; unsigned u = __float_as_uint(x);
    asm("mov.b64 %0, {%1, %1};" : "=l"(r) : "r"(u));
    return r;
}
static __device__ __forceinline__ void unpack2(u64 v, float& lo, float& hi) {
    unsigned a, b;
    asm("mov.b64 {%0, %1}, %2;" : "=r"(a), "=r"(b) : "l"(v));
    lo = __uint_as_float(a);
    hi = __uint_as_float(b);
}

// ---------------------------------------------------------------------------
__global__ void zero_acc_kernel() {
    int t = blockIdx.x * blockDim.x + threadIdx.x;
    if (t < 1280) ACC[t] = 0.0f;
}

// ---------------------------------------------------------------------------
__global__ __launch_bounds__(TPB, 2) void gram_kernel(
    const float* __restrict__ X, const float* __restrict__ Y,
    int ntiles, int N)
{
    extern __shared__ char smem[];
    const uint32_t sb = s2u(smem);

    const int tid = threadIdx.x;
    const int w   = tid >> 5;      // warp 0..7 (row-uniform owner: rows r%8==w)
    const int l   = tid & 31;
    const int bi  = (l >> 2) & 3;  // i block: i0 = 8*bi  (8 rows of G)
    const int bj  = l & 3;         // j block
    const int jh  = l >> 4;        // j half: j0 = 8*bj + 4*jh (4 cols of G)
    const int jq4 = 2 * bj + jh;   // float4 column of the j vector

    // accumulators: acc[p][q] is f32x2 for G rows (8bi+2p, 8bi+2p+1), col j0+q
    u64 acc[4][4];
#pragma unroll
    for (int p = 0; p < 4; p++)
#pragma unroll
        for (int q = 0; q < 4; q++) acc[p][q] = 0ull;

    float cacc[4] = {0.f, 0.f, 0.f, 0.f};
    float sxacc = 0.f;
    float ys[4] = {0.f, 0.f, 0.f, 0.f};

    const float4* X4 = (const float4*)X;
    const float4* Y4 = (const float4*)Y;
    const long long total4 = (long long)N * 8;
    const int nloc = (ntiles > (int)blockIdx.x)
                     ? (ntiles - 1 - (int)blockIdx.x) / (int)gridDim.x + 1 : 0;

    // stage local tile i into buffer (i&1); zero-fill out-of-range chunks
    auto stage = [&](int i) {
        long long g = (long long)blockIdx.x + (long long)i * gridDim.x;
        int p = i & 1;
        long long gi = g * 512 + tid;
        uint32_t dx = sb + RAWX_OFF + p * 8192 + tid * 16;
        float4 z = make_float4(0.f, 0.f, 0.f, 0.f);
        if (gi < total4) CP16(dx, X4 + gi);
        else *(float4*)(smem + RAWX_OFF + p * 8192 + tid * 16) = z;
        if (gi + 256 < total4) CP16(dx + 4096, X4 + gi + 256);
        else *(float4*)(smem + RAWX_OFF + p * 8192 + tid * 16 + 4096) = z;
        if (tid < 64) {
            long long gy = g * 64 + tid;
            if (gy < N) CP16(sb + RAWY_OFF + p * 1024 + tid * 16, Y4 + gy);
            else *(float4*)(smem + RAWY_OFF + p * 1024 + tid * 16) = z;
        }
        CP_COMMIT();
    };

    if (nloc > 0) stage(0);

    for (int i = 0; i < nloc; i++) {
        const int p = i & 1;
        if (i + 1 < nloc) { stage(i + 1); CP_WAIT1(); } else { CP_WAIT0(); }
        __syncthreads();

        const float4*     rx  = (const float4*)(smem + RAWX_OFF + p * 8192);
        const ulonglong2* rxu = (const ulonglong2*)rx;
        const float*      sx  = (const float*)rx;
        const float4*     sy  = (const float4*)(smem + RAWY_OFF + p * 1024);

        // ---- G pass: rows r = w + 8k (row-uniform warp -> broadcast LDS) ----
#pragma unroll
        for (int k = 0; k < 8; k++) {
            const int r = w + 8 * k;
            ulonglong2 ia = rxu[r * 8 + 2 * bi];      // (x[i0],x[i0+1]) (x[i0+2],x[i0+3])
            ulonglong2 ib = rxu[r * 8 + 2 * bi + 1];  // (x[i0+4..7]) pairs
            float4     jv = rx [r * 8 + jq4];         // x[j0..j0+3]
            u64 ap[4] = {ia.x, ia.y, ib.x, ib.y};
            u64 bd[4] = {dup2(jv.x), dup2(jv.y), dup2(jv.z), dup2(jv.w)};
#pragma unroll
            for (int pp = 0; pp < 4; pp++)
#pragma unroll
                for (int q = 0; q < 4; q++) ffma2(acc[pp][q], ap[pp], bd[q]);
        }

        // ---- c pass: rows r = w + 8k; lane l = column i ----
#pragma unroll
        for (int k = 0; k < 8; k++) {
            const int r = w + 8 * k;
            float  x  = sx[r * 32 + l];
            float4 y4 = sy[r];
            cacc[0] += x * y4.x;
            cacc[1] += x * y4.y;
            cacc[2] += x * y4.z;
            cacc[3] += x * y4.w;
            sxacc += x;
            if (l == 0) { ys[0] += y4.x; ys[1] += y4.y; ys[2] += y4.z; ys[3] += y4.w; }
        }
        __syncthreads();
    }

    // ---- epilogue: per-warp G slice into smem, then reduce + atomics ----
    {
        float* mg = (float*)(smem + SG_OFF) + w * 1024;
        const int j0 = 8 * bj + 4 * jh;
#pragma unroll
        for (int pp = 0; pp < 4; pp++) {
            const int i0 = 8 * bi + 2 * pp;
#pragma unroll
            for (int q = 0; q < 4; q++) {
                float lo, hi;
                unpack2(acc[pp][q], lo, hi);
                mg[i0 * 32 + j0 + q]       = lo;
                mg[(i0 + 1) * 32 + j0 + q] = hi;
            }
        }
        float* scp = (float*)(smem + SCP_OFF) + w * 128;
#pragma unroll
        for (int m = 0; m < 4; m++) scp[l * 4 + m] = cacc[m];
        ((float*)(smem + SXP_OFF))[w * 32 + l] = sxacc;
        if (l == 0) {
#pragma unroll
            for (int m = 0; m < 4; m++) ((float*)(smem + SYP_OFF))[w * 4 + m] = ys[m];
        }
    }
    __syncthreads();

    {
        const float* sg = (const float*)(smem + SG_OFF);
        for (int e = tid; e < 1024; e += TPB) {
            float s = 0.f;
#pragma unroll
            for (int ww = 0; ww < 8; ww++) s += sg[ww * 1024 + e];
            atomicAdd(&ACC[e], s);
        }
        if (tid < 128) {
            const float* scp = (const float*)(smem + SCP_OFF);
            float s = 0.f;
#pragma unroll
            for (int ww = 0; ww < 8; ww++) s += scp[ww * 128 + tid];
            atomicAdd(&ACC[1056 + tid], s);
        }
        if (tid < 32) {
            const float* sxp = (const float*)(smem + SXP_OFF);
            float s = 0.f;
#pragma unroll
            for (int ww = 0; ww < 8; ww++) s += sxp[ww * 32 + tid];
            atomicAdd(&ACC[1024 + tid], s);
        }
        if (tid < 4) {
            const float* syp = (const float*)(smem + SYP_OFF);
            float s = 0.f;
#pragma unroll
            for (int ww = 0; ww < 8; ww++) s += syp[ww * 4 + tid];
            atomicAdd(&ACC[1184 + tid], s);
        }
    }
}

// ---------------------------------------------------------------------------
__global__ __launch_bounds__(256) void solve_kernel(float* __restrict__ out, float Nf)
{
    __shared__ float G[33 * 33];
    __shared__ float c[132];
    __shared__ float Z[132];
    __shared__ float rowsum[33];
    __shared__ float stepSh;

    const int tid = threadIdx.x;
    for (int e = tid; e < 1024; e += 256) {
        int i = e >> 5, j = e & 31;
        G[i * 33 + j] = ACC[e];
    }
    if (tid < 32) {
        float s = ACC[1024 + tid];
        G[tid * 33 + 32] = s;
        G[32 * 33 + tid] = s;
    }
    if (tid == 0) G[32 * 33 + 32] = Nf;
    if (tid < 128) c[tid] = ACC[1056 + tid];
    if (tid >= 128 && tid < 132) c[tid] = ACC[1184 + (tid - 128)];
    if (tid < 132) Z[tid] = 0.0f;
    __syncthreads();

    if (tid < 33) {
        float s = 0.f;
        for (int j = 0; j < 33; j++) s += fabsf(G[tid * 33 + j]);
        rowsum[tid] = s;
    }
    __syncthreads();
    if (tid == 0) {
        float L = 0.f;
        for (int i = 0; i < 33; i++) L = fmaxf(L, rowsum[i]);
        stepSh = 1.0f / L;
    }
    __syncthreads();
    const float step = stepSh;

    const int i = tid >> 2, m = tid & 3;
    for (int it = 0; it < PGD_ITERS; it++) {
        float zn = 0.f;
        if (tid < 132) {
            float dot = 0.f;
#pragma unroll
            for (int j = 0; j < 33; j++) dot += G[i * 33 + j] * Z[j * 4 + m];
            zn = Z[tid] - step * (dot - c[tid]);
            if (i < 32) zn = fmaxf(zn, 0.0f);
        }
        __syncthreads();
        if (tid < 132) Z[tid] = zn;
        __syncthreads();
    }
    if (tid < 128) out[tid] = Z[tid];
}

// ---------------------------------------------------------------------------
extern "C" void kernel_launch(void* const* d_in, const int* in_sizes, int n_in,
                              void* d_out, int out_size)
{
    const float* X = (const float*)d_in[0];
    const float* Y = (const float*)d_in[1];
    const int N = in_sizes[0] / 32;
    const int ntiles = (N + TROWS - 1) / TROWS;

    cudaFuncSetAttribute(gram_kernel,
                         cudaFuncAttributeMaxDynamicSharedMemorySize, SMEMSZ);

    zero_acc_kernel<<<5, 256>>>();
    gram_kernel<<<NCTA, TPB, SMEMSZ>>>(X, Y, ntiles, N);
    solve_kernel<<<1, 256>>>((float*)d_out, (float)N);
}